// round 3
// baseline (speedup 1.0000x reference)
#include <cuda_runtime.h>
#include <cuda_bf16.h>

// Problem constants
#define BATCH  4
#define CH     256
#define IMG    256
#define NGROUP 32
#define CPG    8      // channels per group
#define WSZ    8      // window size
#define NT     64     // tokens per window
#define NHEAD  8
#define DHEAD  32
#define GN_EPS 1e-5f

// GroupNorm stats scratch (device globals: no allocation allowed)
__device__ float g_mean[BATCH * NGROUP];
__device__ float g_rstd[BATCH * NGROUP];

// ---------------------------------------------------------------------------
// Kernel 1: GroupNorm statistics. One block per (b, g).
// Group g covers channels [g*8, g*8+8), contiguous in x's layout, so each
// (b,g) reduces a contiguous chunk of 8*IMG*IMG floats.
// ---------------------------------------------------------------------------
__global__ void gn_stats_kernel(const float* __restrict__ x)
{
    const int bg = blockIdx.x;                       // 0..127
    const float4* p = reinterpret_cast<const float4*>(x + (size_t)bg * CPG * IMG * IMG);
    const int n4 = (CPG * IMG * IMG) / 4;            // 131072

    float s = 0.f, sq = 0.f;
    for (int i = threadIdx.x; i < n4; i += blockDim.x) {
        float4 v = p[i];
        s  += v.x + v.y + v.z + v.w;
        sq += v.x * v.x + v.y * v.y + v.z * v.z + v.w * v.w;
    }
    for (int o = 16; o; o >>= 1) {
        s  += __shfl_down_sync(0xFFFFFFFFu, s,  o);
        sq += __shfl_down_sync(0xFFFFFFFFu, sq, o);
    }
    __shared__ float ss[32], ssq[32];
    const int w = threadIdx.x >> 5, l = threadIdx.x & 31;
    if (l == 0) { ss[w] = s; ssq[w] = sq; }
    __syncthreads();
    if (w == 0) {
        const int nw = blockDim.x >> 5;
        s  = (l < nw) ? ss[l]  : 0.f;
        sq = (l < nw) ? ssq[l] : 0.f;
        for (int o = 16; o; o >>= 1) {
            s  += __shfl_down_sync(0xFFFFFFFFu, s,  o);
            sq += __shfl_down_sync(0xFFFFFFFFu, sq, o);
        }
        if (l == 0) {
            const float invN = 1.f / (float)(CPG * IMG * IMG);
            const float m   = s * invN;
            const float var = sq * invN - m * m;      // biased variance
            g_mean[bg] = m;
            g_rstd[bg] = rsqrtf(var + GN_EPS);
        }
    }
}

// ---------------------------------------------------------------------------
// Kernel 2: fully fused window attention. One block per 8x8 window.
//
// Shared memory layout (floats), total 52224 floats = 208896 bytes:
//   XIN [64][260]  normalized window input (pad 260 -> float4-aligned rows)
//   OF  [64][260]  concatenated per-head attention output
//   WP  [256][33]  staged weight panel, k-major (bank-conflict-free)
//   QS/KS/VS [64][33] per-head Q,K,V (QS reused as out-proj staging)
//   SS  [64][65]   attention scores
// ---------------------------------------------------------------------------
#define XIN_OFF 0
#define OF_OFF  16640
#define WP_OFF  33280
#define QS_OFF  41728
#define KS_OFF  43840
#define VS_OFF  45952
#define SS_OFF  48064
#define SMEM_FLOATS 52224

__global__ void __launch_bounds__(256, 1)
win_attn_kernel(const float* __restrict__ x,
                const float* __restrict__ gnw, const float* __restrict__ gnb,
                const float* __restrict__ Wq,  const float* __restrict__ Wk,
                const float* __restrict__ Wv,  const float* __restrict__ Wo,
                const float* __restrict__ bo,  const float* __restrict__ pos,
                const float* __restrict__ scale,
                float* __restrict__ out)
{
    extern __shared__ float sm[];
    float* XIN = sm + XIN_OFF;
    float* OF  = sm + OF_OFF;
    float* WP  = sm + WP_OFF;
    float* QS  = sm + QS_OFF;
    float* KS  = sm + KS_OFF;
    float* VS  = sm + VS_OFF;
    float* SS  = sm + SS_OFF;

    const int tid = threadIdx.x;
    const int bid = blockIdx.x;               // 4096 windows
    const int b   = bid >> 10;
    const int wh  = (bid >> 5) & 31;
    const int ww  = bid & 31;
    const size_t xbase = (size_t)b * CH * IMG * IMG;
    const int    hw0   = (wh * WSZ) * IMG + ww * WSZ;

    // ---- load window + apply GroupNorm ----
    for (int idx = tid; idx < NT * CH; idx += 256) {
        const int c = idx >> 6;               // channel
        const int t = idx & 63;               // token
        const int off = hw0 + ((t >> 3) * IMG) + (t & 7);
        const float v = x[xbase + (size_t)c * IMG * IMG + off];
        const int g = c >> 3;
        const float xn = (v - g_mean[b * NGROUP + g]) * g_rstd[b * NGROUP + g]
                         * gnw[c] + gnb[c];
        XIN[t * 260 + c] = xn;
    }
    __syncthreads();

    const float qscale = scale[0];
    const int oc      = tid & 31;             // output channel within 32-panel
    const int tokBase = (tid >> 5) * 8;       // 8 tokens per thread

    // Stage a 32-row weight panel (rows [row0,row0+32) of a 256x256 matrix)
    // into WP as k-major [k][oc] with pad 33. Global reads coalesced.
    auto load_panel = [&](const float* __restrict__ Wsrc, int row0) {
        for (int idx = tid; idx < 32 * 256; idx += 256) {
            const int po = idx >> 8;          // panel output channel 0..31
            const int k  = idx & 255;
            WP[k * 33 + po] = Wsrc[(size_t)(row0 + po) * 256 + k];
        }
    };

    // dst[t*33+oc] = mul * sum_k A[t*260+k] * WP[k*33+oc]    (64x32, k=256)
    auto gemm_panel = [&](const float* __restrict__ A, float* __restrict__ dst,
                          float mul) {
        float acc[8];
        #pragma unroll
        for (int i = 0; i < 8; i++) acc[i] = 0.f;
        for (int k = 0; k < 256; k += 4) {
            const float w0 = WP[(k + 0) * 33 + oc];
            const float w1 = WP[(k + 1) * 33 + oc];
            const float w2 = WP[(k + 2) * 33 + oc];
            const float w3 = WP[(k + 3) * 33 + oc];
            #pragma unroll
            for (int i = 0; i < 8; i++) {
                const float4 a = *reinterpret_cast<const float4*>(
                    &A[(tokBase + i) * 260 + k]);
                acc[i] = fmaf(a.x, w0, acc[i]);
                acc[i] = fmaf(a.y, w1, acc[i]);
                acc[i] = fmaf(a.z, w2, acc[i]);
                acc[i] = fmaf(a.w, w3, acc[i]);
            }
        }
        #pragma unroll
        for (int i = 0; i < 8; i++)
            dst[(tokBase + i) * 33 + oc] = acc[i] * mul;
    };

    // ---- per-head attention ----
    for (int h = 0; h < NHEAD; h++) {
        const int r0 = h * DHEAD;

        load_panel(Wq, r0); __syncthreads();
        gemm_panel(XIN, QS, qscale); __syncthreads();

        load_panel(Wk, r0); __syncthreads();
        gemm_panel(XIN, KS, 1.f); __syncthreads();

        load_panel(Wv, r0); __syncthreads();
        gemm_panel(XIN, VS, 1.f); __syncthreads();

        // S = Q K^T + pos_emb[h]   (64x64, k=32). 4x4 register tile/thread.
        {
            const int i0 = (tid >> 4) * 4;
            const int j0 = (tid & 15) * 4;
            float a[16];
            #pragma unroll
            for (int z = 0; z < 16; z++) a[z] = 0.f;
            for (int d = 0; d < DHEAD; d++) {
                float qv[4], kv[4];
                #pragma unroll
                for (int ii = 0; ii < 4; ii++) qv[ii] = QS[(i0 + ii) * 33 + d];
                #pragma unroll
                for (int jj = 0; jj < 4; jj++) kv[jj] = KS[(j0 + jj) * 33 + d];
                #pragma unroll
                for (int ii = 0; ii < 4; ii++)
                    #pragma unroll
                    for (int jj = 0; jj < 4; jj++)
                        a[ii * 4 + jj] = fmaf(qv[ii], kv[jj], a[ii * 4 + jj]);
            }
            #pragma unroll
            for (int ii = 0; ii < 4; ii++)
                #pragma unroll
                for (int jj = 0; jj < 4; jj++)
                    SS[(i0 + ii) * 65 + (j0 + jj)] =
                        a[ii * 4 + jj] + pos[((h * 64) + i0 + ii) * 64 + j0 + jj];
        }
        __syncthreads();

        // row softmax (one row per thread, threads 0..63)
        if (tid < 64) {
            float m = -1e30f;
            for (int j = 0; j < 64; j++) m = fmaxf(m, SS[tid * 65 + j]);
            float s = 0.f;
            for (int j = 0; j < 64; j++) {
                const float e = __expf(SS[tid * 65 + j] - m);
                SS[tid * 65 + j] = e;
                s += e;
            }
            const float inv = 1.f / s;
            for (int j = 0; j < 64; j++) SS[tid * 65 + j] *= inv;
        }
        __syncthreads();

        // O_h = S @ V_h  -> OF[t][h*32+oc]   (64x32, k=64)
        {
            float acc[8];
            #pragma unroll
            for (int i = 0; i < 8; i++) acc[i] = 0.f;
            for (int k = 0; k < 64; k++) {
                const float vv = VS[k * 33 + oc];
                #pragma unroll
                for (int i = 0; i < 8; i++)
                    acc[i] = fmaf(SS[(tokBase + i) * 65 + k], vv, acc[i]);
            }
            #pragma unroll
            for (int i = 0; i < 8; i++)
                OF[(tokBase + i) * 260 + r0 + oc] = acc[i];
        }
        __syncthreads();
    }

    // ---- output projection + bias + residual, 8 panels of 32 channels ----
    for (int cp = 0; cp < 8; cp++) {
        load_panel(Wo, cp * 32); __syncthreads();
        gemm_panel(OF, QS, 1.f);             // stage result in QS
        __syncthreads();
        for (int idx = tid; idx < NT * 32; idx += 256) {
            const int cl = idx >> 6;          // local channel 0..31
            const int t  = idx & 63;
            const int c  = cp * 32 + cl;
            const int off = hw0 + ((t >> 3) * IMG) + (t & 7);
            const size_t ga = xbase + (size_t)c * IMG * IMG + off;
            out[ga] = QS[t * 33 + cl] + bo[c] + x[ga];
        }
        __syncthreads();
    }
}

// ---------------------------------------------------------------------------
extern "C" void kernel_launch(void* const* d_in, const int* in_sizes, int n_in,
                              void* d_out, int out_size)
{
    const float* x    = (const float*)d_in[0];
    const float* gnw  = (const float*)d_in[1];
    const float* gnb  = (const float*)d_in[2];
    const float* Wq   = (const float*)d_in[3];
    const float* Wk   = (const float*)d_in[4];
    const float* Wv   = (const float*)d_in[5];
    const float* Wo   = (const float*)d_in[6];
    const float* bo   = (const float*)d_in[7];
    const float* pos  = (const float*)d_in[8];
    const float* scl  = (const float*)d_in[9];
    float* out = (float*)d_out;

    const int smem_bytes = SMEM_FLOATS * sizeof(float); // 208896
    cudaFuncSetAttribute(win_attn_kernel,
                         cudaFuncAttributeMaxDynamicSharedMemorySize,
                         smem_bytes);

    gn_stats_kernel<<<BATCH * NGROUP, 512>>>(x);
    win_attn_kernel<<<BATCH * (IMG / WSZ) * (IMG / WSZ), 256, smem_bytes>>>(
        x, gnw, gnb, Wq, Wk, Wv, Wo, bo, pos, scl, out);
}